// round 6
// baseline (speedup 1.0000x reference)
#include <cuda_runtime.h>
#include <cstdint>

#define N_TOK 131072
#define DIM   64
#define QSTG  8
#define KCB   1024

#define TM       128              // tokens per CTA
#define TKC      128              // codewords per chunk
#define CPS      (KCB / TKC)      // 8 chunks per stage
#define NCHUNKS  (QSTG * CPS)     // 64
#define NTHREADS 256

typedef unsigned long long ull;
typedef unsigned int uint;

// ---- dynamic smem layout (floats) ----
// sB[2] : TKC rows x 68 floats (272B rows, 16B-aligned for cp.async)
// sA    : TM rows x 66 floats
// redV/redI : [TM][16]
#define SB_ROWF   68
#define BUF_F     (TKC * SB_ROWF)            // 8704 floats / buffer
#define SA_ROWF   66
#define SA_OFF    (2 * BUF_F)                // 17408
#define REDV_OFF  (SA_OFF + TM * SA_ROWF)
#define REDI_OFF  (REDV_OFF + TM * 16)
#define SMEM_FLOATS (REDI_OFF + TM * 16)
#define SMEM_BYTES  (SMEM_FLOATS * 4)        // ~120 KB

__device__ double g_loss[QSTG];
__device__ float  g_cnorm[QSTG * KCB];

__device__ __forceinline__ void ffma2(ull& d, ull a, ull b) {
    asm("fma.rn.f32x2 %0, %1, %2, %0;" : "+l"(d) : "l"(a), "l"(b));
}
__device__ __forceinline__ float2 unpack2(ull v) {
    float2 r;
    asm("mov.b64 {%0, %1}, %2;" : "=f"(r.x), "=f"(r.y) : "l"(v));
    return r;
}
__device__ __forceinline__ void cp_async16(uint dst, const void* src) {
    asm volatile("cp.async.cg.shared.global [%0], [%1], 16;" :: "r"(dst), "l"(src));
}
__device__ __forceinline__ void cp_commit() {
    asm volatile("cp.async.commit_group;");
}
template <int N>
__device__ __forceinline__ void cp_wait() {
    asm volatile("cp.async.wait_group %0;" :: "n"(N));
}

// ---------------------------------------------------------------------------
__global__ void prep_kernel(const float* __restrict__ cb) {
    int k = blockIdx.x * blockDim.x + threadIdx.x;
    if (k < QSTG * KCB) {
        const float* p = cb + (size_t)k * DIM;
        float s0 = 0.f, s1 = 0.f, s2 = 0.f, s3 = 0.f;
#pragma unroll
        for (int d = 0; d < DIM; d += 4) {
            s0 = __fadd_rn(s0, __fmul_rn(p[d + 0], p[d + 0]));
            s1 = __fadd_rn(s1, __fmul_rn(p[d + 1], p[d + 1]));
            s2 = __fadd_rn(s2, __fmul_rn(p[d + 2], p[d + 2]));
            s3 = __fadd_rn(s3, __fmul_rn(p[d + 3], p[d + 3]));
        }
        g_cnorm[k] = __fadd_rn(__fadd_rn(s0, s1), __fadd_rn(s2, s3));
    }
    if (blockIdx.x == 0 && threadIdx.x < QSTG) g_loss[threadIdx.x] = 0.0;
}

// ---------------------------------------------------------------------------
// 16B async staging of one 128x64 codeword chunk (coalesced 512B/warp-instr)
// ---------------------------------------------------------------------------
__device__ __forceinline__ void prefetch_chunk(uint buf_base, const float* src,
                                               int tid) {
#pragma unroll
    for (int s = 0; s < 8; ++s) {
        int tau = tid + NTHREADS * s;        // 0..2047
        int k = tau >> 4, i = tau & 15;
        cp_async16(buf_base + (uint)k * (SB_ROWF * 4) + (uint)i * 16,
                   (const char*)src + (size_t)tau * 16);
    }
    cp_commit();
}

// ---------------------------------------------------------------------------
// fused 8-stage VQ; argmin value replicates reference rounding pipeline:
// val = (rn - 2*dot) + cn, rn via 4-lane partials (verified 0-flip in R1)
// ---------------------------------------------------------------------------
__global__ void __launch_bounds__(NTHREADS, 1)
vq_kernel(const float* __restrict__ x, const float* __restrict__ cb,
          float* __restrict__ out) {
    extern __shared__ float sm[];
    float* sA   = sm + SA_OFF;
    float* redV = sm + REDV_OFF;
    int*   redI = (int*)(sm + REDI_OFF);
    __shared__ int   finIdx[TM];
    __shared__ float wsum[NTHREADS / 32];

    const int tid  = threadIdx.x;
    const int tokg = tid >> 4;     // 0..15 : 8 tokens each
    const int cwg  = tid & 15;     // 0..15 : k = cwg + 16*j
    const int n0   = blockIdx.x * TM;

    const uint smem_base = (uint)__cvta_generic_to_shared((void*)sm);

    float* out_xq  = out;
    float* out_idx = out + (size_t)N_TOK * DIM;

    // ---- prefetch chunks 0, 1 ----
    prefetch_chunk(smem_base, cb, tid);
    prefetch_chunk(smem_base + BUF_F * 4, cb + (size_t)TKC * DIM, tid);

    // ---- stage token tile into padded sA (once) ----
    {
        const int t = tid >> 1, hd = tid & 1;
        const float2* xr = (const float2*)(x + (size_t)(n0 + t) * DIM + hd * 32);
        float2* ar = (float2*)(sA + t * SA_ROWF + hd * 32);
#pragma unroll
        for (int m = 0; m < 16; ++m) ar[m] = xr[m];
    }
    __syncthreads();   // sA visible for rn compute below

    for (int q = 0; q < QSTG; ++q) {
        // ---- per-token ||r||^2, 4-lane partials (matches reference rounding) ----
        float rn[8];
#pragma unroll
        for (int ti = 0; ti < 8; ++ti) {
            const float* r = sA + (tokg * 8 + ti) * SA_ROWF;
            float s0 = 0.f, s1 = 0.f, s2 = 0.f, s3 = 0.f;
#pragma unroll
            for (int d = 0; d < DIM; d += 4) {
                s0 = __fadd_rn(s0, __fmul_rn(r[d + 0], r[d + 0]));
                s1 = __fadd_rn(s1, __fmul_rn(r[d + 1], r[d + 1]));
                s2 = __fadd_rn(s2, __fmul_rn(r[d + 2], r[d + 2]));
                s3 = __fadd_rn(s3, __fmul_rn(r[d + 3], r[d + 3]));
            }
            rn[ti] = __fadd_rn(__fadd_rn(s0, s1), __fadd_rn(s2, s3));
        }

        float bestv[8];
        int   besti[8];
#pragma unroll
        for (int i = 0; i < 8; ++i) { bestv[i] = 3.4e38f; besti[i] = 0; }

        for (int ch = 0; ch < CPS; ++ch) {
            const int c = q * CPS + ch;
            const float* sB = sm + (c & 1) * BUF_F;

            if (c == NCHUNKS - 1) cp_wait<0>(); else cp_wait<1>();
            __syncthreads();   // chunk c resident

            // ---- mainloop: 8 tokens x 8 codewords, d-paired accumulators ----
            ull acc[64];
#pragma unroll
            for (int i = 0; i < 64; ++i) acc[i] = 0ull;

            const float* aBase = sA + tokg * 8 * SA_ROWF;
            const float* bBase = sB + cwg * SB_ROWF;
#pragma unroll 4
            for (int d2 = 0; d2 < DIM / 2; ++d2) {
                ull a2[8], b2[8];
#pragma unroll
                for (int ti = 0; ti < 8; ++ti)
                    a2[ti] = *(const ull*)(aBase + ti * SA_ROWF + 2 * d2);
#pragma unroll
                for (int j = 0; j < 8; ++j)
                    b2[j] = *(const ull*)(bBase + j * 16 * SB_ROWF + 2 * d2);
#pragma unroll
                for (int ti = 0; ti < 8; ++ti)
#pragma unroll
                    for (int j = 0; j < 8; ++j)
                        ffma2(acc[ti * 8 + j], a2[ti], b2[j]);
            }
            __syncthreads();   // all reads of buffer (c&1) complete

            // ---- refill freed buffer with chunk c+2 ----
            if (c + 2 < NCHUNKS)
                prefetch_chunk(smem_base + (c & 1) * (BUF_F * 4),
                               cb + (size_t)(c + 2) * TKC * DIM, tid);

            // ---- running argmin: val = (rn - 2*dot) + cn  (R1-exact) ----
#pragma unroll
            for (int j = 0; j < 8; ++j) {
                const int kk = ch * TKC + cwg + 16 * j;     // stage-local k
                const float cn = __ldg(&g_cnorm[q * KCB + kk]);
#pragma unroll
                for (int ti = 0; ti < 8; ++ti) {
                    float2 p  = unpack2(acc[ti * 8 + j]);
                    float dot = __fadd_rn(p.x, p.y);
                    float v   = __fadd_rn(__fsub_rn(rn[ti], __fmul_rn(2.0f, dot)), cn);
                    bool lt = v < bestv[ti];
                    bestv[ti] = lt ? v : bestv[ti];
                    besti[ti] = lt ? kk : besti[ti];
                }
            }
        }
        __syncthreads();

        // ---- cross-thread argmin (16 partials per token, index tiebreak) ----
#pragma unroll
        for (int ti = 0; ti < 8; ++ti) {
            int t = tokg * 8 + ti;
            redV[t * 16 + cwg] = bestv[ti];
            redI[t * 16 + cwg] = besti[ti];
        }
        __syncthreads();
        if (tid < TM) {
            const float* rv = redV + tid * 16;
            const int*   ri = redI + tid * 16;
            float bv = rv[0];
            int   bi = ri[0];
#pragma unroll
            for (int g = 1; g < 16; ++g) {
                float v  = rv[g];
                int   ii = ri[g];
                if (v < bv || (v == bv && ii < bi)) { bv = v; bi = ii; }
            }
            finIdx[tid] = bi;
            out_idx[(size_t)(n0 + tid) * QSTG + q] = (float)bi;
        }
        __syncthreads();

        // ---- residual update (in padded sA) + commitment loss ----
        {
            const int t = tid >> 1, hd = tid & 1;
            const int idx = finIdx[t];
            const float4* c4 =
                (const float4*)(cb + (size_t)q * KCB * DIM + (size_t)idx * DIM + hd * 32);
            float2* r2 = (float2*)(sA + t * SA_ROWF + hd * 32);
            float ls = 0.f;
#pragma unroll
            for (int m = 0; m < 8; ++m) {
                float4 cv = c4[m];
                float2 ra = r2[2 * m], rb = r2[2 * m + 1];
                float2 na, nb;
                na.x = __fsub_rn(ra.x, cv.x);
                na.y = __fsub_rn(ra.y, cv.y);
                nb.x = __fsub_rn(rb.x, cv.z);
                nb.y = __fsub_rn(rb.y, cv.w);
                r2[2 * m]     = na;
                r2[2 * m + 1] = nb;
                ls = fmaf(na.x, na.x, ls);
                ls = fmaf(na.y, na.y, ls);
                ls = fmaf(nb.x, nb.x, ls);
                ls = fmaf(nb.y, nb.y, ls);
            }
#pragma unroll
            for (int off = 16; off; off >>= 1)
                ls += __shfl_down_sync(0xffffffff, ls, off);
            if ((tid & 31) == 0) wsum[tid >> 5] = ls;
            __syncthreads();
            if (tid == 0) {
                float tot = 0.f;
#pragma unroll
                for (int w = 0; w < NTHREADS / 32; ++w) tot += wsum[w];
                atomicAdd(&g_loss[q], (double)tot);
            }
        }
        __syncthreads();   // sA update complete before next stage's rn compute
    }

    // ---- xq = x - final_residual ----
    {
        const int t = tid >> 1, hd = tid & 1;
        const float2* xr = (const float2*)(x + (size_t)(n0 + t) * DIM + hd * 32);
        const float2* rr = (const float2*)(sA + t * SA_ROWF + hd * 32);
        float2* o2 = (float2*)(out_xq + (size_t)(n0 + t) * DIM + hd * 32);
#pragma unroll
        for (int m = 0; m < 16; ++m) {
            float2 xv = xr[m], rv = rr[m], ov;
            ov.x = __fsub_rn(xv.x, rv.x);
            ov.y = __fsub_rn(xv.y, rv.y);
            o2[m] = ov;
        }
    }
}

// ---------------------------------------------------------------------------
__global__ void loss_kernel(float* __restrict__ out) {
    if (threadIdx.x < QSTG)
        out[(size_t)N_TOK * DIM + (size_t)N_TOK * QSTG + threadIdx.x] =
            (float)(g_loss[threadIdx.x] / (double)((size_t)N_TOK * DIM));
}

extern "C" void kernel_launch(void* const* d_in, const int* in_sizes, int n_in,
                              void* d_out, int out_size) {
    const float* x  = (const float*)d_in[0];
    const float* cb = (const float*)d_in[1];
    if (n_in >= 2 && in_sizes[0] == QSTG * KCB * DIM && in_sizes[1] == N_TOK * DIM) {
        const float* t = x; x = cb; cb = t;
    }
    float* out = (float*)d_out;

    cudaFuncSetAttribute(vq_kernel,
                         cudaFuncAttributeMaxDynamicSharedMemorySize, SMEM_BYTES);

    prep_kernel<<<(QSTG * KCB + 255) / 256, 256>>>(cb);
    vq_kernel<<<N_TOK / TM, NTHREADS, SMEM_BYTES>>>(x, cb, out);
    loss_kernel<<<1, 32>>>(out);
}

// round 7
// speedup vs baseline: 1.0712x; 1.0712x over previous
#include <cuda_runtime.h>
#include <cstdint>

#define N_TOK 131072
#define DIM   64
#define QSTG  8
#define KCB   1024

#define TM       128             // tokens per CTA
#define TKC      256             // codewords per chunk
#define NCHUNKS  32              // global chunks = QSTG * (KCB/TKC)
#define NTHREADS 256

typedef unsigned long long ull;
typedef unsigned int uint;

// ---- dynamic smem layout (floats) ----
// sB[2] : 64 d-rows x 1024 B each (row d holds 128 k-pairs (B[2p][d],B[2p+1][d])
//         at 8B slot (p ^ (d>>2)))  -> 16384 floats per buffer
// sA    : [TM][66]  (stride 66: the two tokg broadcast rows land 16 banks apart)
// redV/redI : [TM][16]
#define BUF_F    (64 * 256)                 // 16384 floats per sB buffer
#define SA_ROWF  66
#define SA_OFF   (2 * BUF_F)                // 32768
#define REDV_OFF (SA_OFF + TM * SA_ROWF)    // 32768 + 8448 = 41216
#define REDI_OFF (REDV_OFF + TM * 16)
#define SMEM_FLOATS (REDI_OFF + TM * 16)
#define SMEM_BYTES  (SMEM_FLOATS * 4)       // 181248 B

__device__ double g_loss[QSTG];
__device__ float  g_cnorm[QSTG * KCB];

__device__ __forceinline__ void ffma2(ull& d, ull a, ull b) {
    asm("fma.rn.f32x2 %0, %1, %2, %0;" : "+l"(d) : "l"(a), "l"(b));
}
__device__ __forceinline__ ull dup2(float a) {
    ull r; unsigned u = __float_as_uint(a);
    asm("mov.b64 %0, {%1, %1};" : "=l"(r) : "r"(u));
    return r;
}
__device__ __forceinline__ float2 unpack2(ull v) {
    float2 r;
    asm("mov.b64 {%0, %1}, %2;" : "=f"(r.x), "=f"(r.y) : "l"(v));
    return r;
}

// ---------------------------------------------------------------------------
__global__ void prep_kernel(const float* __restrict__ cb) {
    int k = blockIdx.x * blockDim.x + threadIdx.x;
    if (k < QSTG * KCB) {
        const float* p = cb + (size_t)k * DIM;
        float s0 = 0.f, s1 = 0.f, s2 = 0.f, s3 = 0.f;
#pragma unroll
        for (int d = 0; d < DIM; d += 4) {
            s0 = __fadd_rn(s0, __fmul_rn(p[d + 0], p[d + 0]));
            s1 = __fadd_rn(s1, __fmul_rn(p[d + 1], p[d + 1]));
            s2 = __fadd_rn(s2, __fmul_rn(p[d + 2], p[d + 2]));
            s3 = __fadd_rn(s3, __fmul_rn(p[d + 3], p[d + 3]));
        }
        g_cnorm[k] = __fadd_rn(__fadd_rn(s0, s1), __fadd_rn(s2, s3));
    }
    if (blockIdx.x == 0 && threadIdx.x < QSTG) g_loss[threadIdx.x] = 0.0;
}

// ---------------------------------------------------------------------------
// synchronous staging of one 256x64 codeword chunk into transposed-pair layout
// (byte-identical to the verified R2 staging)
// ---------------------------------------------------------------------------
__device__ __forceinline__ void stage_chunk(float* buf, const float* gsrc, int tid) {
    const float4* gb = (const float4*)gsrc;
#pragma unroll
    for (int it = 0; it < 8; ++it) {
        int L  = it * NTHREADS + tid;    // 0..2047
        int p  = L >> 4;                 // pair index 0..127
        int dq = L & 15;                 // d quad 0..15
        float4 v1 = gb[(2 * p) * 16 + dq];
        float4 v2 = gb[(2 * p + 1) * 16 + dq];
        const float* a1 = &v1.x;
        const float* a2 = &v2.x;
        int swz = p ^ dq;
#pragma unroll
        for (int m = 0; m < 4; ++m) {
            float2* dst = (float2*)((char*)buf + (size_t)(4 * dq + m) * 1024) + swz;
            *dst = make_float2(a1[m], a2[m]);
        }
    }
}

// ---------------------------------------------------------------------------
// fused 8-stage VQ: R2 mainloop, double-buffered B, staging overlapped with
// the argmin epilogue
// ---------------------------------------------------------------------------
__global__ void __launch_bounds__(NTHREADS, 1)
vq_kernel(const float* __restrict__ x, const float* __restrict__ cb,
          float* __restrict__ out) {
    extern __shared__ float sm[];
    float* sA   = sm + SA_OFF;
    float* redV = sm + REDV_OFF;
    int*   redI = (int*)(sm + REDI_OFF);
    __shared__ int   finIdx[TM];
    __shared__ float wsum[NTHREADS / 32];

    const int tid  = threadIdx.x;
    const int tokg = tid >> 4;    // 0..15 : 8 tokens each
    const int cwg  = tid & 15;    // 0..15 : 8 k-pairs each (p = cwg + 16j)
    const int n0   = blockIdx.x * TM;

    float* out_xq  = out;
    float* out_idx = out + (size_t)N_TOK * DIM;

    // ---- stage chunk 0 + load token tile ----
    stage_chunk(sm, cb, tid);
    {
        const int t = tid >> 1, hd = tid & 1;
        const float2* xr = (const float2*)(x + (size_t)(n0 + t) * DIM + hd * 32);
        float2* ar = (float2*)(sA + t * SA_ROWF + hd * 32);
#pragma unroll
        for (int m = 0; m < 16; ++m) ar[m] = xr[m];
    }
    __syncthreads();

    for (int q = 0; q < QSTG; ++q) {
        float bestv[8];
        int   besti[8];
#pragma unroll
        for (int i = 0; i < 8; ++i) { bestv[i] = 3.4e38f; besti[i] = 0; }

        for (int ch = 0; ch < 4; ++ch) {
            const int c = q * 4 + ch;
            const float* sB = sm + (c & 1) * BUF_F;

            // ---- mainloop: 8 tokens x 8 k-pairs (R2-exact) ----
            ull acc[64];
#pragma unroll
            for (int i = 0; i < 64; ++i) acc[i] = 0ull;

            const float* aTok = sA + tokg * 8 * SA_ROWF;
#pragma unroll 4
            for (int d = 0; d < DIM; ++d) {
                ull a2r[8];
#pragma unroll
                for (int ti = 0; ti < 8; ++ti)
                    a2r[ti] = dup2(aTok[ti * SA_ROWF + d]);
                const ull* bRow = (const ull*)((char*)sB + (size_t)d * 1024)
                                  + (cwg ^ (d >> 2));
                ull b2r[8];
#pragma unroll
                for (int j = 0; j < 8; ++j) b2r[j] = bRow[16 * j];
#pragma unroll
                for (int ti = 0; ti < 8; ++ti)
#pragma unroll
                    for (int j = 0; j < 8; ++j)
                        ffma2(acc[ti * 8 + j], a2r[ti], b2r[j]);
            }
            __syncthreads();   // all warps done reading sB[c&1] / sA

            // ---- stage chunk c+1 into the other buffer; its LDG latency
            //      overlaps the argmin epilogue below (no barrier until loop end)
            if (c + 1 < NCHUNKS)
                stage_chunk(sm + ((c + 1) & 1) * BUF_F,
                            cb + (size_t)(c + 1) * TKC * DIM, tid);

            // ---- running argmin: val = cnorm - 2*dot (R2-exact pipeline) ----
#pragma unroll
            for (int j = 0; j < 8; ++j) {
                const int kl = 2 * (cwg + 16 * j);        // within-chunk k
                const int kg = ch * TKC + kl;             // stage-local k
                const float2 cn = __ldg((const float2*)&g_cnorm[(size_t)c * TKC + kl]);
#pragma unroll
                for (int ti = 0; ti < 8; ++ti) {
                    float2 p = unpack2(acc[ti * 8 + j]);
                    float v0 = fmaf(-2.0f, p.x, cn.x);
                    float v1 = fmaf(-2.0f, p.y, cn.y);
                    bool l0 = v0 < bestv[ti];
                    bestv[ti] = l0 ? v0 : bestv[ti];
                    besti[ti] = l0 ? kg : besti[ti];
                    bool l1 = v1 < bestv[ti];
                    bestv[ti] = l1 ? v1 : bestv[ti];
                    besti[ti] = l1 ? (kg + 1) : besti[ti];
                }
            }
            __syncthreads();   // staging STS complete before next mainloop
        }

        // ---- cross-thread argmin (16 partials per token, index tiebreak) ----
#pragma unroll
        for (int ti = 0; ti < 8; ++ti) {
            int t = tokg * 8 + ti;
            redV[t * 16 + cwg] = bestv[ti];
            redI[t * 16 + cwg] = besti[ti];
        }
        __syncthreads();
        if (tid < TM) {
            const float* rv = redV + tid * 16;
            const int*   ri = redI + tid * 16;
            float bv = rv[0];
            int   bi = ri[0];
#pragma unroll
            for (int g = 1; g < 16; ++g) {
                float v  = rv[g];
                int   ii = ri[g];
                if (v < bv || (v == bv && ii < bi)) { bv = v; bi = ii; }
            }
            finIdx[tid] = bi;
            out_idx[(size_t)(n0 + tid) * QSTG + q] = (float)bi;
        }
        __syncthreads();

        // ---- residual update (in padded sA) + commitment loss ----
        {
            const int t = tid >> 1, hd = tid & 1;
            const int idx = finIdx[t];
            const float4* c4 =
                (const float4*)(cb + (size_t)q * KCB * DIM + (size_t)idx * DIM + hd * 32);
            float2* r2 = (float2*)(sA + t * SA_ROWF + hd * 32);
            float ls = 0.f;
#pragma unroll
            for (int m = 0; m < 8; ++m) {
                float4 cv = c4[m];
                float2 ra = r2[2 * m], rb = r2[2 * m + 1];
                float2 na, nb;
                na.x = __fsub_rn(ra.x, cv.x);
                na.y = __fsub_rn(ra.y, cv.y);
                nb.x = __fsub_rn(rb.x, cv.z);
                nb.y = __fsub_rn(rb.y, cv.w);
                r2[2 * m]     = na;
                r2[2 * m + 1] = nb;
                ls = fmaf(na.x, na.x, ls);
                ls = fmaf(na.y, na.y, ls);
                ls = fmaf(nb.x, nb.x, ls);
                ls = fmaf(nb.y, nb.y, ls);
            }
#pragma unroll
            for (int off = 16; off; off >>= 1)
                ls += __shfl_down_sync(0xffffffff, ls, off);
            if ((tid & 31) == 0) wsum[tid >> 5] = ls;
            __syncthreads();
            if (tid == 0) {
                float tot = 0.f;
#pragma unroll
                for (int w = 0; w < NTHREADS / 32; ++w) tot += wsum[w];
                atomicAdd(&g_loss[q], (double)tot);
            }
        }
        __syncthreads();   // sA update visible before next stage's mainloop
    }

    // ---- xq = x - final_residual ----
    {
        const int t = tid >> 1, hd = tid & 1;
        const float2* xr = (const float2*)(x + (size_t)(n0 + t) * DIM + hd * 32);
        const float2* rr = (const float2*)(sA + t * SA_ROWF + hd * 32);
        float2* o2 = (float2*)(out_xq + (size_t)(n0 + t) * DIM + hd * 32);
#pragma unroll
        for (int m = 0; m < 16; ++m) {
            float2 xv = xr[m], rv = rr[m], ov;
            ov.x = __fsub_rn(xv.x, rv.x);
            ov.y = __fsub_rn(xv.y, rv.y);
            o2[m] = ov;
        }
    }
}

// ---------------------------------------------------------------------------
__global__ void loss_kernel(float* __restrict__ out) {
    if (threadIdx.x < QSTG)
        out[(size_t)N_TOK * DIM + (size_t)N_TOK * QSTG + threadIdx.x] =
            (float)(g_loss[threadIdx.x] / (double)((size_t)N_TOK * DIM));
}

extern "C" void kernel_launch(void* const* d_in, const int* in_sizes, int n_in,
                              void* d_out, int out_size) {
    const float* x  = (const float*)d_in[0];
    const float* cb = (const float*)d_in[1];
    if (n_in >= 2 && in_sizes[0] == QSTG * KCB * DIM && in_sizes[1] == N_TOK * DIM) {
        const float* t = x; x = cb; cb = t;
    }
    float* out = (float*)d_out;

    cudaFuncSetAttribute(vq_kernel,
                         cudaFuncAttributeMaxDynamicSharedMemorySize, SMEM_BYTES);

    prep_kernel<<<(QSTG * KCB + 255) / 256, 256>>>(cb);
    vq_kernel<<<N_TOK / TM, NTHREADS, SMEM_BYTES>>>(x, cb, out);
    loss_kernel<<<1, 32>>>(out);
}

// round 8
// speedup vs baseline: 1.1812x; 1.1026x over previous
#include <cuda_runtime.h>
#include <cstdint>

#define N_TOK 131072
#define DIM   64
#define QSTG  8
#define KCB   1024

#define TM       128             // tokens per CTA
#define TKC      256             // codewords per chunk
#define NCHUNKS  32              // QSTG * (KCB/TKC)
#define NTHREADS 256

typedef unsigned long long ull;
typedef unsigned int uint;

#define CHUNK_F  (TKC * DIM)     // 16384 floats = 64KB per chunk image

// ---- dynamic smem layout (floats) ----
// sB[2] : chunk images (64 d-rows x 1024B, pre-transposed/swizzled in g_cbT)
// sA    : [TM][66]  (stride 66: tokg broadcast rows 16 banks apart)
// redV/redI : [TM][16]
#define BUF_F    CHUNK_F
#define SA_ROWF  66
#define SA_OFF   (2 * BUF_F)                 // 32768
#define REDV_OFF (SA_OFF + TM * SA_ROWF)     // 41216
#define REDI_OFF (REDV_OFF + TM * 16)
#define SMEM_FLOATS (REDI_OFF + TM * 16)
#define SMEM_BYTES  (SMEM_FLOATS * 4)        // 181248 B

__device__ double g_loss[QSTG];
__device__ float  g_cnorm[QSTG * KCB];
__device__ float  g_cbT[NCHUNKS * CHUNK_F];  // pre-transposed codebook (2MB)

__device__ __forceinline__ void ffma2(ull& d, ull a, ull b) {
    asm("fma.rn.f32x2 %0, %1, %2, %0;" : "+l"(d) : "l"(a), "l"(b));
}
__device__ __forceinline__ ull dup2(float a) {
    ull r; unsigned u = __float_as_uint(a);
    asm("mov.b64 %0, {%1, %1};" : "=l"(r) : "r"(u));
    return r;
}
__device__ __forceinline__ float2 unpack2(ull v) {
    float2 r;
    asm("mov.b64 {%0, %1}, %2;" : "=f"(r.x), "=f"(r.y) : "l"(v));
    return r;
}
__device__ __forceinline__ void cp_async16(uint dst, const void* src) {
    asm volatile("cp.async.cg.shared.global [%0], [%1], 16;" :: "r"(dst), "l"(src));
}
__device__ __forceinline__ void cp_commit() {
    asm volatile("cp.async.commit_group;");
}
template <int N>
__device__ __forceinline__ void cp_wait() {
    asm volatile("cp.async.wait_group %0;" :: "n"(N));
}

// ---------------------------------------------------------------------------
// prep1: codeword squared norms + zero loss accumulators
// ---------------------------------------------------------------------------
__global__ void prep_kernel(const float* __restrict__ cb) {
    int k = blockIdx.x * blockDim.x + threadIdx.x;
    if (k < QSTG * KCB) {
        const float* p = cb + (size_t)k * DIM;
        float s0 = 0.f, s1 = 0.f, s2 = 0.f, s3 = 0.f;
#pragma unroll
        for (int d = 0; d < DIM; d += 4) {
            s0 = __fadd_rn(s0, __fmul_rn(p[d + 0], p[d + 0]));
            s1 = __fadd_rn(s1, __fmul_rn(p[d + 1], p[d + 1]));
            s2 = __fadd_rn(s2, __fmul_rn(p[d + 2], p[d + 2]));
            s3 = __fadd_rn(s3, __fmul_rn(p[d + 3], p[d + 3]));
        }
        g_cnorm[k] = __fadd_rn(__fadd_rn(s0, s1), __fadd_rn(s2, s3));
    }
    if (blockIdx.x == 0 && threadIdx.x < QSTG) g_loss[threadIdx.x] = 0.0;
}

// ---------------------------------------------------------------------------
// prep2: build g_cbT — the exact smem image of each chunk.
// chunk c, element B[k][d] (k local 0..255) -> row d (1024B), pair p=k>>1,
// 8B slot (p ^ (d>>2)), half (k&1). One block per chunk.
// ---------------------------------------------------------------------------
__global__ void prep2_kernel(const float* __restrict__ cb) {
    const int c   = blockIdx.x;
    const int tid = threadIdx.x;
    const float4* gb = (const float4*)(cb + (size_t)c * CHUNK_F);
    float* buf = g_cbT + (size_t)c * CHUNK_F;
#pragma unroll
    for (int it = 0; it < 8; ++it) {
        int L  = it * NTHREADS + tid;     // 0..2047
        int p  = L >> 4;                  // pair 0..127
        int dq = L & 15;                  // d quad 0..15
        float4 v1 = gb[(2 * p) * 16 + dq];
        float4 v2 = gb[(2 * p + 1) * 16 + dq];
        const float* a1 = &v1.x;
        const float* a2 = &v2.x;
        int swz = p ^ dq;
#pragma unroll
        for (int m = 0; m < 4; ++m) {
            float2* dst = (float2*)((char*)buf + (size_t)(4 * dq + m) * 1024) + swz;
            *dst = make_float2(a1[m], a2[m]);
        }
    }
}

// ---------------------------------------------------------------------------
// register-free chunk staging: contiguous 64KB copy, 16 cp.async per thread
// ---------------------------------------------------------------------------
__device__ __forceinline__ void prefetch_chunk(uint buf_base, int c, int tid) {
    const char* src = (const char*)(g_cbT + (size_t)c * CHUNK_F);
#pragma unroll
    for (int s = 0; s < 16; ++s) {
        int i = tid + NTHREADS * s;       // 16B unit 0..4095
        cp_async16(buf_base + (uint)i * 16, src + (size_t)i * 16);
    }
    cp_commit();
}

// ---------------------------------------------------------------------------
// fused 8-stage VQ: R2 mainloop/epilogue, cp.async double-buffered B
// ---------------------------------------------------------------------------
__global__ void __launch_bounds__(NTHREADS, 1)
vq_kernel(const float* __restrict__ x, const float* __restrict__ cb,
          float* __restrict__ out) {
    extern __shared__ float sm[];
    float* sA   = sm + SA_OFF;
    float* redV = sm + REDV_OFF;
    int*   redI = (int*)(sm + REDI_OFF);
    __shared__ int   finIdx[TM];
    __shared__ float wsum[NTHREADS / 32];

    const int tid  = threadIdx.x;
    const int tokg = tid >> 4;    // 0..15 : 8 tokens each
    const int cwg  = tid & 15;    // 0..15 : 8 k-pairs each (p = cwg + 16j)
    const int n0   = blockIdx.x * TM;

    const uint smem_base = (uint)__cvta_generic_to_shared((void*)sm);

    float* out_xq  = out;
    float* out_idx = out + (size_t)N_TOK * DIM;

    // ---- prefetch chunks 0,1 ; load token tile ----
    prefetch_chunk(smem_base, 0, tid);
    prefetch_chunk(smem_base + BUF_F * 4, 1, tid);
    {
        const int t = tid >> 1, hd = tid & 1;
        const float2* xr = (const float2*)(x + (size_t)(n0 + t) * DIM + hd * 32);
        float2* ar = (float2*)(sA + t * SA_ROWF + hd * 32);
#pragma unroll
        for (int m = 0; m < 16; ++m) ar[m] = xr[m];
    }

    for (int q = 0; q < QSTG; ++q) {
        float bestv[8];
        int   besti[8];
#pragma unroll
        for (int i = 0; i < 8; ++i) { bestv[i] = 3.4e38f; besti[i] = 0; }

        for (int ch = 0; ch < 4; ++ch) {
            const int c = q * 4 + ch;
            const float* sB = sm + (c & 1) * BUF_F;

            if (c == NCHUNKS - 1) cp_wait<0>(); else cp_wait<1>();
            __syncthreads();   // chunk c resident in sB; sA writers done

            // ---- mainloop: 8 tokens x 8 k-pairs (R2-exact) ----
            ull acc[64];
#pragma unroll
            for (int i = 0; i < 64; ++i) acc[i] = 0ull;

            const float* aTok = sA + tokg * 8 * SA_ROWF;
#pragma unroll 4
            for (int d = 0; d < DIM; ++d) {
                ull a2r[8];
#pragma unroll
                for (int ti = 0; ti < 8; ++ti)
                    a2r[ti] = dup2(aTok[ti * SA_ROWF + d]);
                const ull* bRow = (const ull*)((char*)sB + (size_t)d * 1024)
                                  + (cwg ^ (d >> 2));
                ull b2r[8];
#pragma unroll
                for (int j = 0; j < 8; ++j) b2r[j] = bRow[16 * j];
#pragma unroll
                for (int ti = 0; ti < 8; ++ti)
#pragma unroll
                    for (int j = 0; j < 8; ++j)
                        ffma2(acc[ti * 8 + j], a2r[ti], b2r[j]);
            }
            __syncthreads();   // all warps done reading sB[c&1]

            // ---- register-free refill of freed buffer with chunk c+2 ----
            if (c + 2 < NCHUNKS)
                prefetch_chunk(smem_base + (c & 1) * (BUF_F * 4), c + 2, tid);

            // ---- running argmin: val = cnorm - 2*dot (R2-exact pipeline) ----
#pragma unroll
            for (int j = 0; j < 8; ++j) {
                const int kl = 2 * (cwg + 16 * j);        // within-chunk k
                const int kg = ch * TKC + kl;             // stage-local k
                const float2 cn = __ldg((const float2*)&g_cnorm[(size_t)c * TKC + kl]);
#pragma unroll
                for (int ti = 0; ti < 8; ++ti) {
                    float2 p = unpack2(acc[ti * 8 + j]);
                    float v0 = fmaf(-2.0f, p.x, cn.x);
                    float v1 = fmaf(-2.0f, p.y, cn.y);
                    bool l0 = v0 < bestv[ti];
                    bestv[ti] = l0 ? v0 : bestv[ti];
                    besti[ti] = l0 ? kg : besti[ti];
                    bool l1 = v1 < bestv[ti];
                    bestv[ti] = l1 ? v1 : bestv[ti];
                    besti[ti] = l1 ? (kg + 1) : besti[ti];
                }
            }
        }
        __syncthreads();

        // ---- cross-thread argmin (16 partials per token, index tiebreak) ----
#pragma unroll
        for (int ti = 0; ti < 8; ++ti) {
            int t = tokg * 8 + ti;
            redV[t * 16 + cwg] = bestv[ti];
            redI[t * 16 + cwg] = besti[ti];
        }
        __syncthreads();
        if (tid < TM) {
            const float* rv = redV + tid * 16;
            const int*   ri = redI + tid * 16;
            float bv = rv[0];
            int   bi = ri[0];
#pragma unroll
            for (int g = 1; g < 16; ++g) {
                float v  = rv[g];
                int   ii = ri[g];
                if (v < bv || (v == bv && ii < bi)) { bv = v; bi = ii; }
            }
            finIdx[tid] = bi;
            out_idx[(size_t)(n0 + tid) * QSTG + q] = (float)bi;
        }
        __syncthreads();

        // ---- residual update (in padded sA) + commitment loss ----
        {
            const int t = tid >> 1, hd = tid & 1;
            const int idx = finIdx[t];
            const float4* c4 =
                (const float4*)(cb + (size_t)q * KCB * DIM + (size_t)idx * DIM + hd * 32);
            float2* r2 = (float2*)(sA + t * SA_ROWF + hd * 32);
            float ls = 0.f;
#pragma unroll
            for (int m = 0; m < 8; ++m) {
                float4 cv = c4[m];
                float2 ra = r2[2 * m], rb = r2[2 * m + 1];
                float2 na, nb;
                na.x = __fsub_rn(ra.x, cv.x);
                na.y = __fsub_rn(ra.y, cv.y);
                nb.x = __fsub_rn(rb.x, cv.z);
                nb.y = __fsub_rn(rb.y, cv.w);
                r2[2 * m]     = na;
                r2[2 * m + 1] = nb;
                ls = fmaf(na.x, na.x, ls);
                ls = fmaf(na.y, na.y, ls);
                ls = fmaf(nb.x, nb.x, ls);
                ls = fmaf(nb.y, nb.y, ls);
            }
#pragma unroll
            for (int off = 16; off; off >>= 1)
                ls += __shfl_down_sync(0xffffffff, ls, off);
            if ((tid & 31) == 0) wsum[tid >> 5] = ls;
            __syncthreads();
            if (tid == 0) {
                float tot = 0.f;
#pragma unroll
                for (int w = 0; w < NTHREADS / 32; ++w) tot += wsum[w];
                atomicAdd(&g_loss[q], (double)tot);
            }
        }
        // next iteration's post-wait __syncthreads orders sA update vs mainloop
    }
    __syncthreads();

    // ---- xq = x - final_residual ----
    {
        const int t = tid >> 1, hd = tid & 1;
        const float2* xr = (const float2*)(x + (size_t)(n0 + t) * DIM + hd * 32);
        const float2* rr = (const float2*)(sA + t * SA_ROWF + hd * 32);
        float2* o2 = (float2*)(out_xq + (size_t)(n0 + t) * DIM + hd * 32);
#pragma unroll
        for (int m = 0; m < 16; ++m) {
            float2 xv = xr[m], rv = rr[m], ov;
            ov.x = __fsub_rn(xv.x, rv.x);
            ov.y = __fsub_rn(xv.y, rv.y);
            o2[m] = ov;
        }
    }
}

// ---------------------------------------------------------------------------
__global__ void loss_kernel(float* __restrict__ out) {
    if (threadIdx.x < QSTG)
        out[(size_t)N_TOK * DIM + (size_t)N_TOK * QSTG + threadIdx.x] =
            (float)(g_loss[threadIdx.x] / (double)((size_t)N_TOK * DIM));
}

extern "C" void kernel_launch(void* const* d_in, const int* in_sizes, int n_in,
                              void* d_out, int out_size) {
    const float* x  = (const float*)d_in[0];
    const float* cb = (const float*)d_in[1];
    if (n_in >= 2 && in_sizes[0] == QSTG * KCB * DIM && in_sizes[1] == N_TOK * DIM) {
        const float* t = x; x = cb; cb = t;
    }
    float* out = (float*)d_out;

    cudaFuncSetAttribute(vq_kernel,
                         cudaFuncAttributeMaxDynamicSharedMemorySize, SMEM_BYTES);

    prep_kernel<<<(QSTG * KCB + 255) / 256, 256>>>(cb);
    prep2_kernel<<<NCHUNKS, NTHREADS>>>(cb);
    vq_kernel<<<N_TOK / TM, NTHREADS, SMEM_BYTES>>>(x, cb, out);
    loss_kernel<<<1, 32>>>(out);
}

// round 9
// speedup vs baseline: 1.2026x; 1.0182x over previous
#include <cuda_runtime.h>
#include <cstdint>

#define N_TOK 131072
#define DIM   64
#define QSTG  8
#define KCB   1024

#define TM       128            // tokens per CTA
#define TKC      256            // codewords per SMEM chunk
#define NCHUNK   (KCB / TKC)    // 4
#define NTHREADS 256

typedef unsigned long long ull;

// ---- dynamic smem layout (floats) ----
// sBt  : 64 d-rows x 1024 B (row d holds 128 pairs (B[2p][d],B[2p+1][d]),
//        8B slot = p ^ (d>>2))                      : 16384
// sA   : [TM][66]  (stride 66 -> tokg broadcast rows 16 banks apart)
// sCn  : [TKC]
// redV/redI : [TM][16]
#define SBT_F    0
#define SA_ROWF  66
#define SA_F     (64 * 256)                  // 16384
#define SCN_F    (SA_F + TM * SA_ROWF)       // 16384 + 8448 = 24832
#define REDV_F   (SCN_F + TKC)               // 25088
#define REDI_F   (REDV_F + TM * 16)          // 27136
#define SMEM_FLOATS (REDI_F + TM * 16)       // 29184
#define SMEM_BYTES  (SMEM_FLOATS * 4)        // 116736 B

__device__ double g_loss[QSTG];
__device__ float  g_cnorm[QSTG * KCB];

__device__ __forceinline__ void ffma2(ull& d, ull a, ull b) {
    asm("fma.rn.f32x2 %0, %1, %2, %0;" : "+l"(d) : "l"(a), "l"(b));
}
__device__ __forceinline__ ull dup2(float a) {
    ull r; unsigned u = __float_as_uint(a);
    asm("mov.b64 %0, {%1, %1};" : "=l"(r) : "r"(u));
    return r;
}
__device__ __forceinline__ float2 unpack2(ull v) {
    float2 r;
    asm("mov.b64 {%0, %1}, %2;" : "=f"(r.x), "=f"(r.y) : "l"(v));
    return r;
}

// ---------------------------------------------------------------------------
// prep: codeword squared norms + zero loss accumulators
// ---------------------------------------------------------------------------
__global__ void prep_kernel(const float* __restrict__ cb) {
    int k = blockIdx.x * blockDim.x + threadIdx.x;
    if (k < QSTG * KCB) {
        const float* p = cb + (size_t)k * DIM;
        float s0 = 0.f, s1 = 0.f, s2 = 0.f, s3 = 0.f;
#pragma unroll
        for (int d = 0; d < DIM; d += 4) {
            s0 = __fadd_rn(s0, __fmul_rn(p[d + 0], p[d + 0]));
            s1 = __fadd_rn(s1, __fmul_rn(p[d + 1], p[d + 1]));
            s2 = __fadd_rn(s2, __fmul_rn(p[d + 2], p[d + 2]));
            s3 = __fadd_rn(s3, __fmul_rn(p[d + 3], p[d + 3]));
        }
        g_cnorm[k] = __fadd_rn(__fadd_rn(s0, s1), __fadd_rn(s2, s3));
    }
    if (blockIdx.x == 0 && threadIdx.x < QSTG) g_loss[threadIdx.x] = 0.0;
}

// ---------------------------------------------------------------------------
// fused: all 8 VQ stages for one 128-token tile (R2 structure; sA padded)
// ---------------------------------------------------------------------------
__global__ void __launch_bounds__(NTHREADS, 1)
vq_kernel(const float* __restrict__ x, const float* __restrict__ cb,
          float* __restrict__ out) {
    extern __shared__ float sm[];
    float* sBt  = sm + SBT_F;
    float* sA   = sm + SA_F;
    float* sCn  = sm + SCN_F;
    float* redV = sm + REDV_F;
    int*   redI = (int*)(sm + REDI_F);
    __shared__ int   finIdx[TM];
    __shared__ float wsum[NTHREADS / 32];

    const int tid  = threadIdx.x;
    const int tokg = tid >> 4;    // 0..15 : 8 tokens each
    const int cwg  = tid & 15;    // 0..15 : 8 codeword-pairs per chunk
    const int n0   = blockIdx.x * TM;

    float* out_xq  = out;
    float* out_idx = out + (size_t)N_TOK * DIM;

    // ---- load token tile once (into padded sA) ----
    {
        const int t = tid >> 1, hd = tid & 1;
        const float2* xr = (const float2*)(x + (size_t)(n0 + t) * DIM + hd * 32);
        float2* ar = (float2*)(sA + t * SA_ROWF + hd * 32);
#pragma unroll
        for (int m = 0; m < 16; ++m) ar[m] = xr[m];
    }

    for (int q = 0; q < QSTG; ++q) {
        const float* cbq = cb + (size_t)q * KCB * DIM;

        float bestv[8];
        int   besti[8];
#pragma unroll
        for (int ti = 0; ti < 8; ++ti) { bestv[ti] = 3.4e38f; besti[ti] = 0; }

        for (int ch = 0; ch < NCHUNK; ++ch) {
            const int k0 = ch * TKC;
            __syncthreads();   // previous users of sBt / sA writers done

            // ---- stage B chunk as transposed pairs, slot = p ^ (d>>2) ----
            {
                const float4* gb = (const float4*)(cbq + (size_t)k0 * DIM);
#pragma unroll
                for (int it = 0; it < 8; ++it) {
                    int L = it * NTHREADS + tid;       // 0..2047
                    int p  = L >> 4;                   // pair index 0..127
                    int dq = L & 15;                   // d quad 0..15
                    float4 v1 = gb[(2 * p) * 16 + dq];
                    float4 v2 = gb[(2 * p + 1) * 16 + dq];
                    const float* a1 = &v1.x;
                    const float* a2 = &v2.x;
                    int swz = p ^ dq;
#pragma unroll
                    for (int m = 0; m < 4; ++m) {
                        float2* dst = (float2*)((char*)sBt + (size_t)(4 * dq + m) * 1024) + swz;
                        *dst = make_float2(a1[m], a2[m]);
                    }
                }
                sCn[tid] = g_cnorm[q * KCB + k0 + tid];
            }
            __syncthreads();

            // ---- 8 tokens x 8 codeword-pairs register tile ----
            ull acc[64];
#pragma unroll
            for (int c = 0; c < 64; ++c) acc[c] = 0ull;

            const float* aTok = sA + tokg * 8 * SA_ROWF;
#pragma unroll 4
            for (int d = 0; d < DIM; ++d) {
                ull a2r[8];
#pragma unroll
                for (int ti = 0; ti < 8; ++ti)
                    a2r[ti] = dup2(aTok[ti * SA_ROWF + d]);
                const ull* bRow = (const ull*)((char*)sBt + (size_t)d * 1024) + (cwg ^ (d >> 2));
                ull b2r[8];
#pragma unroll
                for (int j = 0; j < 8; ++j) b2r[j] = bRow[16 * j];
#pragma unroll
                for (int ti = 0; ti < 8; ++ti)
#pragma unroll
                    for (int j = 0; j < 8; ++j)
                        ffma2(acc[ti * 8 + j], a2r[ti], b2r[j]);
            }

            // ---- running argmin: val = cnorm - 2*dot ----
#pragma unroll
            for (int j = 0; j < 8; ++j) {
                const int kl = 2 * (cwg + 16 * j);
                const float2 cn = *(const float2*)(sCn + kl);
                const int kg = k0 + kl;
#pragma unroll
                for (int ti = 0; ti < 8; ++ti) {
                    float2 p = unpack2(acc[ti * 8 + j]);
                    float v0 = fmaf(-2.0f, p.x, cn.x);
                    float v1 = fmaf(-2.0f, p.y, cn.y);
                    bool l0 = v0 < bestv[ti];
                    bestv[ti] = l0 ? v0 : bestv[ti];
                    besti[ti] = l0 ? kg : besti[ti];
                    bool l1 = v1 < bestv[ti];
                    bestv[ti] = l1 ? v1 : bestv[ti];
                    besti[ti] = l1 ? (kg + 1) : besti[ti];
                }
            }
        }
        __syncthreads();

        // ---- cross-thread argmin (16 partials per token), index tiebreak ----
#pragma unroll
        for (int ti = 0; ti < 8; ++ti) {
            int t = tokg * 8 + ti;
            redV[t * 16 + cwg] = bestv[ti];
            redI[t * 16 + cwg] = besti[ti];
        }
        __syncthreads();
        if (tid < TM) {
            const float* rv = redV + tid * 16;
            const int*   ri = redI + tid * 16;
            float bv = rv[0];
            int   bi = ri[0];
#pragma unroll
            for (int g = 1; g < 16; ++g) {
                float v  = rv[g];
                int   ii = ri[g];
                if (v < bv || (v == bv && ii < bi)) { bv = v; bi = ii; }
            }
            finIdx[tid] = bi;
            out_idx[(size_t)(n0 + tid) * QSTG + q] = (float)bi;
        }
        __syncthreads();

        // ---- residual update (in padded sA) + commitment loss ----
        {
            const int t = tid >> 1, hd = tid & 1;
            const int idx = finIdx[t];
            const float4* c4 = (const float4*)(cbq + (size_t)idx * DIM + hd * 32);
            float2* r2 = (float2*)(sA + t * SA_ROWF + hd * 32);
            float ls = 0.f;
#pragma unroll
            for (int m = 0; m < 8; ++m) {
                float4 cv = c4[m];
                float2 ra = r2[2 * m], rb = r2[2 * m + 1];
                float2 na, nb;
                na.x = __fsub_rn(ra.x, cv.x);
                na.y = __fsub_rn(ra.y, cv.y);
                nb.x = __fsub_rn(rb.x, cv.z);
                nb.y = __fsub_rn(rb.y, cv.w);
                r2[2 * m]     = na;
                r2[2 * m + 1] = nb;
                ls = fmaf(na.x, na.x, ls);
                ls = fmaf(na.y, na.y, ls);
                ls = fmaf(nb.x, nb.x, ls);
                ls = fmaf(nb.y, nb.y, ls);
            }
#pragma unroll
            for (int off = 16; off; off >>= 1)
                ls += __shfl_down_sync(0xffffffff, ls, off);
            if ((tid & 31) == 0) wsum[tid >> 5] = ls;
            __syncthreads();
            if (tid == 0) {
                float tot = 0.f;
#pragma unroll
                for (int w = 0; w < NTHREADS / 32; ++w) tot += wsum[w];
                atomicAdd(&g_loss[q], (double)tot);
            }
        }
        // next stage's top-of-chunk __syncthreads orders sA writes vs reads
    }
    __syncthreads();

    // ---- xq = x - final_residual ----
    {
        const int t = tid >> 1, hd = tid & 1;
        const float2* xr = (const float2*)(x + (size_t)(n0 + t) * DIM + hd * 32);
        const float2* rr = (const float2*)(sA + t * SA_ROWF + hd * 32);
        float2* o2 = (float2*)(out_xq + (size_t)(n0 + t) * DIM + hd * 32);
#pragma unroll
        for (int m = 0; m < 16; ++m) {
            float2 xv = xr[m], rv = rr[m], ov;
            ov.x = __fsub_rn(xv.x, rv.x);
            ov.y = __fsub_rn(xv.y, rv.y);
            o2[m] = ov;
        }
    }
}

// ---------------------------------------------------------------------------
__global__ void loss_kernel(float* __restrict__ out) {
    if (threadIdx.x < QSTG)
        out[(size_t)N_TOK * DIM + (size_t)N_TOK * QSTG + threadIdx.x] =
            (float)(g_loss[threadIdx.x] / (double)((size_t)N_TOK * DIM));
}

extern "C" void kernel_launch(void* const* d_in, const int* in_sizes, int n_in,
                              void* d_out, int out_size) {
    const float* x  = (const float*)d_in[0];
    const float* cb = (const float*)d_in[1];
    if (n_in >= 2 && in_sizes[0] == QSTG * KCB * DIM && in_sizes[1] == N_TOK * DIM) {
        const float* t = x; x = cb; cb = t;
    }
    float* out = (float*)d_out;

    cudaFuncSetAttribute(vq_kernel,
                         cudaFuncAttributeMaxDynamicSharedMemorySize, SMEM_BYTES);

    prep_kernel<<<(QSTG * KCB + 255) / 256, 256>>>(cb);
    vq_kernel<<<N_TOK / TM, NTHREADS, SMEM_BYTES>>>(x, cb, out);
    loss_kernel<<<1, 32>>>(out);
}